// round 2
// baseline (speedup 1.0000x reference)
#include <cuda_runtime.h>

#define B_TOTAL   262144
#define THREADS   256
#define DIN       100
#define HD        64
#define GG        10
#define NHEADS    5
#define CHUNK     25
#define XPAD      27
#define W0STRIDE  4100   // 4096 + 4 pad: heads land on distinct 4-bank groups
#define TWSTRIDE  65
#define W1STRIDE  68

// shared-memory float offsets
#define OFF_DW0   0                     // 100*64 = 6400
#define OFF_DW1   (OFF_DW0 + 6400)      // 64*64  = 4096
#define OFF_DBW   (OFF_DW1 + 4096)      // 64*12  = 768 (11 padded to 12)
#define OFF_W0    (OFF_DBW + 768)       // 5*4100 = 20500
#define OFF_W1    (OFF_W0  + 20500)     // 5*68   = 340
#define OFF_DB0   (OFF_W1  + 340)       // 64
#define OFF_DB1   (OFF_DB0 + 64)        // 64
#define OFF_DBB   (OFF_DB1 + 64)        // 12
#define OFF_TW0   (OFF_DBB + 12)        // 5*65 = 325
#define OFF_B0    (OFF_TW0 + 325)       // 325
#define OFF_TW1   (OFF_B0  + 325)       // 8
#define OFF_B1    (OFF_TW1 + 8)         // 8
#define OFF_X     (OFF_B1  + 8)         // 256*27 = 6912
#define SMEM_FLOATS (OFF_X + THREADS*XPAD)
#define SMEM_BYTES  (SMEM_FLOATS * 4)

__global__ void __launch_bounds__(THREADS, 1)
drnet_kernel(const float* __restrict__ dosage, const float* __restrict__ x,
             const float* __restrict__ dW0, const float* __restrict__ db0,
             const float* __restrict__ dW1, const float* __restrict__ db1,
             const float* __restrict__ dbW, const float* __restrict__ dbB,
             const float* __restrict__ W0,  const float* __restrict__ tw0,
             const float* __restrict__ b0,  const float* __restrict__ W1,
             const float* __restrict__ tw1, const float* __restrict__ b1,
             float* __restrict__ out, int B)
{
    extern __shared__ float sm[];
    const int tid = threadIdx.x;

    // ---------------- stage weights into shared ----------------
    for (int i = tid; i < 6400; i += THREADS) sm[OFF_DW0 + i] = dW0[i];
    for (int i = tid; i < 4096; i += THREADS) sm[OFF_DW1 + i] = dW1[i];
    for (int i = tid; i < 64 * 11; i += THREADS) {
        int k = i / 11, j = i % 11;
        sm[OFF_DBW + k * 12 + j] = dbW[i];
    }
    for (int i = tid; i < NHEADS * 4096; i += THREADS) {
        int h = i >> 12, r = i & 4095;
        sm[OFF_W0 + h * W0STRIDE + r] = W0[i];
    }
    for (int i = tid; i < NHEADS * 64; i += THREADS) {
        int h = i / 64, j = i % 64;
        sm[OFF_W1 + h * W1STRIDE + j]  = W1[i];
        sm[OFF_TW0 + h * TWSTRIDE + j] = tw0[i];
        sm[OFF_B0  + h * TWSTRIDE + j] = b0[i];
    }
    if (tid < 64) { sm[OFF_DB0 + tid] = db0[tid]; sm[OFF_DB1 + tid] = db1[tid]; }
    if (tid < 11) sm[OFF_DBB + tid] = dbB[tid];
    if (tid < NHEADS) { sm[OFF_TW1 + tid] = tw1[tid]; sm[OFF_B1 + tid] = b1[tid]; }

    const int s = blockIdx.x * THREADS + tid;  // sample id (grid exactly covers B)
    const float t = dosage[s];

    // ---------------- layer0: hidden0 = relu(x @ dW0 + db0) ----------------
    float acc[HD];
    // (bias init after first sync so s_db0 is valid; do it below)
    bool first = true;

    #pragma unroll 1
    for (int c = 0; c < DIN / CHUNK; c++) {
        // stage x chunk [256 samples][25 cols]
        for (int i = tid; i < THREADS * CHUNK; i += THREADS) {
            int r = i / CHUNK, cc = i % CHUNK;
            sm[OFF_X + r * XPAD + cc] =
                x[(blockIdx.x * THREADS + r) * DIN + c * CHUNK + cc];
        }
        __syncthreads();
        if (first) {
            #pragma unroll
            for (int j = 0; j < HD; j++) acc[j] = sm[OFF_DB0 + j];
            first = false;
        }
        #pragma unroll 5
        for (int kk = 0; kk < CHUNK; kk++) {
            float a = sm[OFF_X + tid * XPAD + kk];
            const float4* w4 = (const float4*)(sm + OFF_DW0 + (c * CHUNK + kk) * HD);
            #pragma unroll
            for (int j4 = 0; j4 < HD / 4; j4++) {
                float4 w = w4[j4];
                acc[4*j4+0] += a * w.x;
                acc[4*j4+1] += a * w.y;
                acc[4*j4+2] += a * w.z;
                acc[4*j4+3] += a * w.w;
            }
        }
        __syncthreads();
    }
    #pragma unroll
    for (int j = 0; j < HD; j++) acc[j] = fmaxf(acc[j], 0.0f);

    // ---------------- layer1: hidden = relu(hidden0 @ dW1 + db1) ----------------
    float hid[HD];
    #pragma unroll
    for (int j = 0; j < HD; j++) hid[j] = sm[OFF_DB1 + j];
    #pragma unroll 4
    for (int k = 0; k < HD; k++) {
        float a = acc[k];
        const float4* w4 = (const float4*)(sm + OFF_DW1 + k * HD);
        #pragma unroll
        for (int j4 = 0; j4 < HD / 4; j4++) {
            float4 w = w4[j4];
            hid[4*j4+0] += a * w.x;
            hid[4*j4+1] += a * w.y;
            hid[4*j4+2] += a * w.z;
            hid[4*j4+3] += a * w.w;
        }
    }
    #pragma unroll
    for (int j = 0; j < HD; j++) hid[j] = fmaxf(hid[j], 0.0f);

    // ---------------- Density block: softmax + grid interpolation ----------------
    float logit[GG + 1];
    #pragma unroll
    for (int j = 0; j <= GG; j++) logit[j] = sm[OFF_DBB + j];
    #pragma unroll 4
    for (int k = 0; k < HD; k++) {
        float a = hid[k];
        const float4* w4 = (const float4*)(sm + OFF_DBW + k * 12);
        float4 w0 = w4[0], w1 = w4[1], w2 = w4[2];
        logit[0]  += a * w0.x; logit[1]  += a * w0.y; logit[2] += a * w0.z; logit[3] += a * w0.w;
        logit[4]  += a * w1.x; logit[5]  += a * w1.y; logit[6] += a * w1.z; logit[7] += a * w1.w;
        logit[8]  += a * w2.x; logit[9]  += a * w2.y; logit[10] += a * w2.z;
    }
    float m = logit[0];
    #pragma unroll
    for (int j = 1; j <= GG; j++) m = fmaxf(m, logit[j]);
    float p[GG + 1];
    float psum = 0.0f;
    #pragma unroll
    for (int j = 0; j <= GG; j++) { p[j] = expf(logit[j] - m); psum += p[j]; }
    float pinv = 1.0f / psum;

    float tB = t * (float)GG;
    float U = ceilf(tB);
    float inter = 1.0f - (U - tB);
    int Ui = (int)U;
    int Li = Ui - 1; if (Li < 0) Li = 0;
    float pL = 0.0f, pU = 0.0f;
    #pragma unroll
    for (int j = 0; j <= GG; j++) {
        pL = (j == Li) ? p[j] : pL;
        pU = (j == Ui) ? p[j] : pU;
    }
    pL *= pinv; pU *= pinv;
    float g = pL + (pU - pL) * inter;

    // ---------------- Multi_head: only the selected bucket head ----------------
    int bkt = (int)floorf(t * (float)NHEADS);
    if (bkt < 0) bkt = 0;
    if (bkt > NHEADS - 1) bkt = NHEADS - 1;

    float ho[HD];
    {
        const float* twp = sm + OFF_TW0 + bkt * TWSTRIDE;
        const float* bp  = sm + OFF_B0  + bkt * TWSTRIDE;
        #pragma unroll
        for (int j = 0; j < HD; j++) ho[j] = t * twp[j] + bp[j];
    }
    const float* wh = sm + OFF_W0 + bkt * W0STRIDE;
    #pragma unroll 4
    for (int k = 0; k < HD; k++) {
        float a = hid[k];
        const float4* w4 = (const float4*)(wh + k * HD);
        #pragma unroll
        for (int j4 = 0; j4 < HD / 4; j4++) {
            float4 w = w4[j4];
            ho[4*j4+0] += a * w.x;
            ho[4*j4+1] += a * w.y;
            ho[4*j4+2] += a * w.z;
            ho[4*j4+3] += a * w.w;
        }
    }
    float q = t * sm[OFF_TW1 + bkt] + sm[OFF_B1 + bkt];
    {
        const float4* w14 = (const float4*)(sm + OFF_W1 + bkt * W1STRIDE);
        #pragma unroll
        for (int j4 = 0; j4 < HD / 4; j4++) {
            float4 w = w14[j4];
            q += fmaxf(ho[4*j4+0], 0.0f) * w.x;
            q += fmaxf(ho[4*j4+1], 0.0f) * w.y;
            q += fmaxf(ho[4*j4+2], 0.0f) * w.z;
            q += fmaxf(ho[4*j4+3], 0.0f) * w.w;
        }
    }

    // outputs: g [B] then Q [B,1], concatenated
    out[s]     = g;
    out[B + s] = q;
}

extern "C" void kernel_launch(void* const* d_in, const int* in_sizes, int n_in,
                              void* d_out, int out_size)
{
    const float* dosage = (const float*)d_in[0];
    const float* x      = (const float*)d_in[1];
    const float* dW0    = (const float*)d_in[2];
    const float* db0    = (const float*)d_in[3];
    const float* dW1    = (const float*)d_in[4];
    const float* db1    = (const float*)d_in[5];
    const float* dbW    = (const float*)d_in[6];
    const float* dbB    = (const float*)d_in[7];
    const float* W0     = (const float*)d_in[8];
    const float* tw0    = (const float*)d_in[9];
    const float* b0     = (const float*)d_in[10];
    const float* W1     = (const float*)d_in[11];
    const float* tw1    = (const float*)d_in[12];
    const float* b1     = (const float*)d_in[13];
    float* out = (float*)d_out;

    int B = in_sizes[0];
    int blocks = B / THREADS;

    cudaFuncSetAttribute(drnet_kernel,
                         cudaFuncAttributeMaxDynamicSharedMemorySize, SMEM_BYTES);

    drnet_kernel<<<blocks, THREADS, SMEM_BYTES>>>(
        dosage, x, dW0, db0, dW1, db1, dbW, dbB,
        W0, tw0, b0, W1, tw1, b1, out, B);
}

// round 4
// speedup vs baseline: 1.7711x; 1.7711x over previous
#include <cuda_runtime.h>

#define THREADS   256
#define DIN       100
#define HD        64
#define GG        10
#define NHEADS    5
#define CHUNK     25
#define XPAD      27
#define W0STRIDE  4100   // heads land on disjoint bank groups (4h mod 32 distinct)
#define TWSTRIDE  65

// ---- shared memory layout (float offsets) ----
// persistent region
#define OFF_DW1   0                       // 64*64 = 4096
#define OFF_DBW   (OFF_DW1 + 4096)        // 64*12 = 768
#define OFF_DB0   (OFF_DBW + 768)         // 64   (8B aligned: 4864)
#define OFF_DB1   (OFF_DB0 + 64)          // 64   (4928)
#define OFF_DBB   (OFF_DB1 + 64)          // 16
#define OFF_TW0   (OFF_DBB + 16)          // 5*65 = 325
#define OFF_B0    (OFF_TW0 + 325)         // 325
#define OFF_TW1   (OFF_B0  + 325)         // 8
#define OFF_B1    (OFF_TW1 + 8)           // 8
#define OFF_W1    (OFF_B1  + 8)           // 5*68 = 340
// phase union (16B aligned base)
#define OFF_U     6016
#define OFF_DW0   OFF_U                   // phase A: 100*64 = 6400
#define OFF_X     (OFF_U + 6400)          // phase A: 256*27 = 6912  (ends 13312)
#define OFF_W0    OFF_U                   // phase C: 5*4100 = 20500
#define SMEM_FLOATS (OFF_U + 20500)
#define SMEM_BYTES  (SMEM_FLOATS * 4)     // 106,064 B -> 2 CTAs/SM

typedef unsigned long long ull;
struct u2 { ull x, y; };

#define FFMA2(d, a, b, c) \
    asm("fma.rn.f32x2 %0, %1, %2, %3;" : "=l"(d) : "l"(a), "l"(b), "l"(c))

__device__ __forceinline__ ull splat2(float a) {
    ull r; asm("mov.b64 %0, {%1, %1};" : "=l"(r) : "f"(a)); return r;
}
__device__ __forceinline__ ull pack2(float a, float b) {
    ull r; asm("mov.b64 %0, {%1, %2};" : "=l"(r) : "f"(a), "f"(b)); return r;
}
__device__ __forceinline__ void unpack2(ull v, float& a, float& b) {
    asm("mov.b64 {%0, %1}, %2;" : "=f"(a), "=f"(b) : "l"(v));
}

__global__ void __launch_bounds__(THREADS, 2)
drnet_kernel(const float* __restrict__ dosage, const float* __restrict__ x,
             const float* __restrict__ dW0, const float* __restrict__ db0,
             const float* __restrict__ dW1, const float* __restrict__ db1,
             const float* __restrict__ dbW, const float* __restrict__ dbB,
             const float* __restrict__ W0,  const float* __restrict__ tw0,
             const float* __restrict__ b0,  const float* __restrict__ W1,
             const float* __restrict__ tw1, const float* __restrict__ b1,
             float* __restrict__ out, int B)
{
    extern __shared__ float sm[];
    const int tid = threadIdx.x;

    // ---------------- stage persistent weights + dW0 ----------------
    #pragma unroll 4
    for (int i = tid; i < 6400; i += THREADS) sm[OFF_DW0 + i] = dW0[i];
    #pragma unroll 4
    for (int i = tid; i < 4096; i += THREADS) sm[OFF_DW1 + i] = dW1[i];
    for (int i = tid; i < 64 * 11; i += THREADS) {
        int k = i / 11, j = i % 11;
        sm[OFF_DBW + k * 12 + j] = dbW[i];
    }
    for (int i = tid; i < NHEADS * 64; i += THREADS) {
        int h = i / 64, j = i % 64;
        sm[OFF_W1  + h * 68 + j]       = W1[i];
        sm[OFF_TW0 + h * TWSTRIDE + j] = tw0[i];
        sm[OFF_B0  + h * TWSTRIDE + j] = b0[i];
    }
    if (tid < 64) { sm[OFF_DB0 + tid] = db0[tid]; sm[OFF_DB1 + tid] = db1[tid]; }
    if (tid < 11) sm[OFF_DBB + tid] = dbB[tid];
    if (tid < NHEADS) { sm[OFF_TW1 + tid] = tw1[tid]; sm[OFF_B1 + tid] = b1[tid]; }

    const int s = blockIdx.x * THREADS + tid;
    const float t = dosage[s];

    // ---------------- layer0: acc = x @ dW0 + db0 (packed f32x2) ----------------
    ull accp[32];
    {
        const ull* bp = (const ull*)(sm + OFF_DB0);
        // defer bias init until after first sync (db0 staged above, fenced by sync below)
        bool first = true;
        #pragma unroll 1
        for (int c = 0; c < DIN / CHUNK; c++) {
            for (int i = tid; i < THREADS * CHUNK; i += THREADS) {
                int r = i / CHUNK, cc = i % CHUNK;
                sm[OFF_X + r * XPAD + cc] =
                    x[(blockIdx.x * THREADS + r) * DIN + c * CHUNK + cc];
            }
            __syncthreads();
            if (first) {
                #pragma unroll
                for (int i = 0; i < 32; i++) accp[i] = bp[i];
                first = false;
            }
            #pragma unroll
            for (int kk = 0; kk < CHUNK; kk++) {
                ull av = splat2(sm[OFF_X + tid * XPAD + kk]);
                const u2* w = (const u2*)(sm + OFF_DW0 + (c * CHUNK + kk) * HD);
                #pragma unroll
                for (int j = 0; j < 16; j++) {
                    u2 ww = w[j];
                    FFMA2(accp[2*j+0], av, ww.x, accp[2*j+0]);
                    FFMA2(accp[2*j+1], av, ww.y, accp[2*j+1]);
                }
            }
            __syncthreads();
        }
    }
    // unpack + relu -> hidden0 scalars (register-resident, const-indexed only)
    float a0[HD];
    #pragma unroll
    for (int i = 0; i < 32; i++) {
        float lo, hi; unpack2(accp[i], lo, hi);
        a0[2*i+0] = fmaxf(lo, 0.0f);
        a0[2*i+1] = fmaxf(hi, 0.0f);
    }

    // ---------------- stage W0 into union (union dead after last layer0 sync) ----
    #pragma unroll 4
    for (int i = tid; i < NHEADS * 4096; i += THREADS) {
        int h = i >> 12, r = i & 4095;
        sm[OFF_W0 + h * W0STRIDE + r] = W0[i];
    }

    // ---------------- layer1 in two 32-output halves (packed) ----------------
    float hid[HD];
    #pragma unroll
    for (int half = 0; half < 2; half++) {
        ull hp[16];
        const ull* bp = (const ull*)(sm + OFF_DB1) + half * 16;
        #pragma unroll
        for (int i = 0; i < 16; i++) hp[i] = bp[i];
        #pragma unroll
        for (int k = 0; k < HD; k++) {
            ull av = splat2(a0[k]);
            const u2* w = (const u2*)(sm + OFF_DW1 + k * HD + half * 32);
            #pragma unroll
            for (int j = 0; j < 8; j++) {
                u2 ww = w[j];
                FFMA2(hp[2*j+0], av, ww.x, hp[2*j+0]);
                FFMA2(hp[2*j+1], av, ww.y, hp[2*j+1]);
            }
        }
        #pragma unroll
        for (int i = 0; i < 16; i++) {
            float lo, hi; unpack2(hp[i], lo, hi);
            hid[half*32 + 2*i+0] = fmaxf(lo, 0.0f);
            hid[half*32 + 2*i+1] = fmaxf(hi, 0.0f);
        }
    }

    // ---------------- density block ----------------
    float logit[GG + 1];
    #pragma unroll
    for (int j = 0; j <= GG; j++) logit[j] = sm[OFF_DBB + j];
    #pragma unroll
    for (int k = 0; k < HD; k++) {
        float a = hid[k];
        const float4* w4 = (const float4*)(sm + OFF_DBW + k * 12);
        float4 w0 = w4[0], w1 = w4[1], w2 = w4[2];
        logit[0] += a * w0.x; logit[1] += a * w0.y; logit[2]  += a * w0.z; logit[3] += a * w0.w;
        logit[4] += a * w1.x; logit[5] += a * w1.y; logit[6]  += a * w1.z; logit[7] += a * w1.w;
        logit[8] += a * w2.x; logit[9] += a * w2.y; logit[10] += a * w2.z;
    }
    float m = logit[0];
    #pragma unroll
    for (int j = 1; j <= GG; j++) m = fmaxf(m, logit[j]);
    float p[GG + 1]; float psum = 0.0f;
    #pragma unroll
    for (int j = 0; j <= GG; j++) { p[j] = expf(logit[j] - m); psum += p[j]; }
    float pinv = 1.0f / psum;

    float tB = t * (float)GG;
    float U = ceilf(tB);
    float inter = 1.0f - (U - tB);
    int Ui = (int)U;
    int Li = Ui - 1; if (Li < 0) Li = 0;
    float pL = 0.0f, pU = 0.0f;
    #pragma unroll
    for (int j = 0; j <= GG; j++) {
        pL = (j == Li) ? p[j] : pL;
        pU = (j == Ui) ? p[j] : pU;
    }
    pL *= pinv; pU *= pinv;
    float g = pL + (pU - pL) * inter;

    __syncthreads();   // W0 staging complete before head reads it

    // ---------------- head (selected bucket), two 32-output halves ----------
    int bkt = (int)floorf(t * (float)NHEADS);
    if (bkt < 0) bkt = 0;
    if (bkt > NHEADS - 1) bkt = NHEADS - 1;

    const float* wh  = sm + OFF_W0  + bkt * W0STRIDE;
    const float* twp = sm + OFF_TW0 + bkt * TWSTRIDE;
    const float* bbp = sm + OFF_B0  + bkt * TWSTRIDE;
    float q = t * sm[OFF_TW1 + bkt] + sm[OFF_B1 + bkt];

    #pragma unroll
    for (int half = 0; half < 2; half++) {
        ull hop[16];
        #pragma unroll
        for (int i = 0; i < 16; i++) {
            int j = half * 32 + 2 * i;
            hop[i] = pack2(fmaf(t, twp[j],   bbp[j]),
                           fmaf(t, twp[j+1], bbp[j+1]));
        }
        #pragma unroll
        for (int k = 0; k < HD; k++) {
            ull av = splat2(hid[k]);
            const u2* w = (const u2*)(wh + k * HD + half * 32);
            #pragma unroll
            for (int j = 0; j < 8; j++) {
                u2 ww = w[j];
                FFMA2(hop[2*j+0], av, ww.x, hop[2*j+0]);
                FFMA2(hop[2*j+1], av, ww.y, hop[2*j+1]);
            }
        }
        const float* w1p = sm + OFF_W1 + bkt * 68 + half * 32;
        #pragma unroll
        for (int i = 0; i < 16; i++) {
            float lo, hi; unpack2(hop[i], lo, hi);
            q += fmaxf(lo, 0.0f) * w1p[2*i+0];
            q += fmaxf(hi, 0.0f) * w1p[2*i+1];
        }
    }

    out[s]     = g;
    out[B + s] = q;
}

extern "C" void kernel_launch(void* const* d_in, const int* in_sizes, int n_in,
                              void* d_out, int out_size)
{
    const float* dosage = (const float*)d_in[0];
    const float* x      = (const float*)d_in[1];
    const float* dW0    = (const float*)d_in[2];
    const float* db0    = (const float*)d_in[3];
    const float* dW1    = (const float*)d_in[4];
    const float* db1    = (const float*)d_in[5];
    const float* dbW    = (const float*)d_in[6];
    const float* dbB    = (const float*)d_in[7];
    const float* W0     = (const float*)d_in[8];
    const float* tw0    = (const float*)d_in[9];
    const float* b0     = (const float*)d_in[10];
    const float* W1     = (const float*)d_in[11];
    const float* tw1    = (const float*)d_in[12];
    const float* b1     = (const float*)d_in[13];
    float* out = (float*)d_out;

    int B = in_sizes[0];
    int blocks = B / THREADS;

    cudaFuncSetAttribute(drnet_kernel,
                         cudaFuncAttributeMaxDynamicSharedMemorySize, SMEM_BYTES);

    drnet_kernel<<<blocks, THREADS, SMEM_BYTES>>>(
        dosage, x, dW0, db0, dW1, db1, dbW, dbB,
        W0, tw0, b0, W1, tw1, b1, out, B);
}